// round 7
// baseline (speedup 1.0000x reference)
#include <cuda_runtime.h>
#include <cuda_bf16.h>
#include <math.h>
#include <stdint.h>

#define HW 10000
#define PW 104
#define PPX (PW*PW)

__device__ float g_buf[1280000];
__device__ float g_q[1280000];
__device__ float g_q2[1280000];
__device__ float g_ref[240000];
__device__ float g_swl[320000];
__device__ float g_featT[2962080];
__device__ float g_part[51200];
__device__ float g_mv[256];

__device__ unsigned short g_bqp_h[PPX*128], g_bqp_l[PPX*128];
__device__ unsigned short g_sfp_h[PPX*256], g_sfp_l[PPX*256];
__device__ unsigned short g_m1p_h[PPX*512], g_m1p_l[PPX*512];
__device__ unsigned short g_m2p_h[PPX*512], g_m2p_l[PPX*512];
__device__ unsigned short g_q2p_h[PPX*128], g_q2p_l[PPX*128];
__device__ unsigned short g_w1_h[409600],  g_w1_l[409600];
__device__ unsigned short g_w2_h[1179648], g_w2_l[1179648];
__device__ unsigned short g_w3_h[262144],  g_w3_l[262144];
__device__ unsigned short g_w4_h[589824],  g_w4_l[589824];
__device__ unsigned short g_w5_h[409600],  g_w5_l[409600];

#define L0_OFF 0
#define L1_OFF 2230272
#define L2_OFF 2787840
#define L3_OFF 2927232

__device__ __forceinline__ float gelu_exact(float x) {
    return 0.5f * x * (1.0f + erff(x * 0.7071067811865475f));
}
__device__ __forceinline__ void split_bf16(float v, unsigned short& h, unsigned short& l) {
    __nv_bfloat16 bh = __float2bfloat16(v);
    float r = v - __bfloat162float(bh);
    __nv_bfloat16 bl = __float2bfloat16(r);
    h = __bfloat16_as_ushort(bh);
    l = __bfloat16_as_ushort(bl);
}
__device__ __forceinline__ void mma_bf16(float* c, const uint32_t* a, uint32_t b0, uint32_t b1) {
    asm volatile(
        "mma.sync.aligned.m16n8k16.row.col.f32.bf16.bf16.f32 "
        "{%0,%1,%2,%3}, {%4,%5,%6,%7}, {%8,%9}, {%0,%1,%2,%3};"
        : "+f"(c[0]), "+f"(c[1]), "+f"(c[2]), "+f"(c[3])
        : "r"(a[0]), "r"(a[1]), "r"(a[2]), "r"(a[3]), "r"(b0), "r"(b1));
}

__device__ __forceinline__ void wprep_one(const float* w, unsigned short* wh,
                                          unsigned short* wl, int CO, int CIN, int KK, int s) {
    int co = s / (CIN * KK);
    int rem = s - co * (CIN * KK);
    int ci = rem / KK;
    int t = rem - ci * KK;
    unsigned short h, l;
    split_bf16(w[s], h, l);
    long d = ((long)t * CO + co) * CIN + ci;
    wh[d] = h; wl[d] = l;
}

__global__ void wprep_all(const float* __restrict__ w1, const float* __restrict__ w2,
                          const float* __restrict__ w3, const float* __restrict__ w4,
                          const float* __restrict__ w5,
                          unsigned short* w1h, unsigned short* w1l,
                          unsigned short* w2h, unsigned short* w2l,
                          unsigned short* w3h, unsigned short* w3l,
                          unsigned short* w4h, unsigned short* w4l,
                          unsigned short* w5h, unsigned short* w5l) {
    const int N1 = 409600, N2 = 1179648, N3 = 262144, N4 = 589824, N5 = 409600;
    int idx = blockIdx.x * blockDim.x + threadIdx.x;
    if (idx < N1) wprep_one(w1, w1h, w1l, 128, 128, 25, idx);
    else if (idx < N1 + N2) wprep_one(w2, w2h, w2l, 512, 256, 9, idx - N1);
    else if (idx < N1 + N2 + N3) wprep_one(w3, w3h, w3l, 512, 512, 1, idx - N1 - N2);
    else if (idx < N1 + N2 + N3 + N4) wprep_one(w4, w4h, w4l, 128, 512, 9, idx - N1 - N2 - N3);
    else if (idx < N1 + N2 + N3 + N4 + N5) wprep_one(w5, w5h, w5l, 128, 128, 25, idx - N1 - N2 - N3 - N4);
}

__global__ void padsplit_cm_kernel(const float* __restrict__ src,
                                   unsigned short* __restrict__ dh, unsigned short* __restrict__ dl) {
    int ppx = blockIdx.x;
    int c = threadIdx.x;
    int py = ppx / PW, px = ppx % PW;
    int y = py - 2, x = px - 2;
    float v = 0.0f;
    if (y >= 0 && y < 100 && x >= 0 && x < 100) v = src[c * HW + y * 100 + x];
    unsigned short h, l;
    split_bf16(v, h, l);
    dh[(long)ppx * 128 + c] = h;
    dl[(long)ppx * 128 + c] = l;
}

__device__ __forceinline__ void tpose_one(const float* src, float* dst, int Hl, int Wl, int idx) {
    int hw = Hl * Wl;
    int n = idx / (132 * hw);
    int r = idx - n * 132 * hw;
    int c = r / hw;
    int p = r - c * hw;
    dst[(n * hw + p) * 132 + c] = src[idx];
}

__global__ void transpose_all(const float* __restrict__ f0, const float* __restrict__ f1,
                              const float* __restrict__ f2, const float* __restrict__ f3,
                              float* __restrict__ featT) {
    const int T0 = 2230272, T1 = 557568, T2 = 139392, T3 = 34848;
    int idx = blockIdx.x * blockDim.x + threadIdx.x;
    if (idx < T0) tpose_one(f0, featT + L0_OFF, 32, 88, idx);
    else if (idx < T0 + T1) tpose_one(f1, featT + L1_OFF, 16, 44, idx - T0);
    else if (idx < T0 + T1 + T2) tpose_one(f2, featT + L2_OFF, 8, 22, idx - T0 - T1);
    else if (idx < T0 + T1 + T2 + T3) tpose_one(f3, featT + L3_OFF, 4, 11, idx - T0 - T1 - T2);
}

// implicit-GEMM conv: block 256thr = 8 warps = 4 co-groups x 2 row-groups.
// Block tile: 128co x (2 rows x 40 px). Warp tile: 32co x 1 row x 40px (5 ntiles).
// RES: 0 none, 1 channel-last resid, 2 channel-major resid. WF: write fp32. WS: write split padded.
template<int CIN, int CO, int K, int PAD, int ACT, int RES, int WF, int WS>
__global__ void __launch_bounds__(256)
conv_mma_kernel(const unsigned short* __restrict__ inp_h, const unsigned short* __restrict__ inp_l,
                const unsigned short* __restrict__ w_h, const unsigned short* __restrict__ w_l,
                const float* __restrict__ bias, const float* __restrict__ resid,
                float* __restrict__ outf,
                unsigned short* __restrict__ oh, unsigned short* __restrict__ ol) {
    constexpr int KK = K * K;
    constexpr int XW = (40 + (K - 1)) | 1;
    constexpr int RWS = 2 + (K - 1);
    constexpr int NPX = RWS * XW;
    constexpr int PA = 2 - PAD;
    constexpr int RWRD = CIN >> 1;

    __shared__ uint32_t s_h[NPX * 12];
    __shared__ uint32_t s_l[NPX * 12];

    int tid = threadIdx.x;
    int warp = tid >> 5;
    int g = warp >> 2;            // row group 0/1
    int lane = tid & 31;
    int lq = lane & 3;
    int lr = lane >> 2;

    int nb = blockIdx.x;          // 0..149
    int y0 = (nb / 3) * 2;
    int x0 = (nb % 3) * 40;
    int coB = blockIdx.y * 128 + (warp & 3) * 32;

    const uint32_t* Wh = (const uint32_t*)w_h;
    const uint32_t* Wl = (const uint32_t*)w_l;

    float acc[2][5][4];
    #pragma unroll
    for (int m = 0; m < 2; m++)
        #pragma unroll
        for (int n = 0; n < 5; n++) {
            acc[m][n][0] = 0.f; acc[m][n][1] = 0.f; acc[m][n][2] = 0.f; acc[m][n][3] = 0.f;
        }

    uint32_t ah[2][4], al[2][4], nh[2][4], nl[2][4];

    for (int ch = 0; ch < CIN / 16; ch++) {
        int ci0 = ch * 16;
        __syncthreads();
        for (int p = tid; p < NPX; p += 256) {
            int r = p / XW;
            int xx = p - r * XW;
            int prow = y0 + r + PA;
            int pcol = x0 + xx + PA;
            uint4 vh0, vh1, vl0, vl1;
            if (pcol < PW) {
                const uint4* gh = (const uint4*)(inp_h + ((long)(prow * PW + pcol) * CIN + ci0));
                const uint4* gl = (const uint4*)(inp_l + ((long)(prow * PW + pcol) * CIN + ci0));
                vh0 = gh[0]; vh1 = gh[1]; vl0 = gl[0]; vl1 = gl[1];
            } else {
                vh0 = make_uint4(0,0,0,0); vh1 = vh0; vl0 = vh0; vl1 = vh0;
            }
            *(uint4*)(s_h + p * 12) = vh0;
            *(uint4*)(s_h + p * 12 + 4) = vh1;
            *(uint4*)(s_l + p * 12) = vl0;
            *(uint4*)(s_l + p * 12 + 4) = vl1;
        }
        __syncthreads();

        int kw = (ci0 >> 1) + lq;
        #pragma unroll
        for (int mt = 0; mt < 2; mt++) {
            long rb = ((long)0 * CO + (coB + mt * 16 + lr)) * RWRD + kw;
            ah[mt][0] = Wh[rb];                al[mt][0] = Wl[rb];
            ah[mt][1] = Wh[rb + 8 * RWRD];     al[mt][1] = Wl[rb + 8 * RWRD];
            ah[mt][2] = Wh[rb + 4];            al[mt][2] = Wl[rb + 4];
            ah[mt][3] = Wh[rb + 8 * RWRD + 4]; al[mt][3] = Wl[rb + 8 * RWRD + 4];
        }

        #pragma unroll 1
        for (int tap = 0; tap < KK; tap++) {
            if (tap + 1 < KK) {
                #pragma unroll
                for (int mt = 0; mt < 2; mt++) {
                    long rb = ((long)(tap + 1) * CO + (coB + mt * 16 + lr)) * RWRD + kw;
                    nh[mt][0] = Wh[rb];                nl[mt][0] = Wl[rb];
                    nh[mt][1] = Wh[rb + 8 * RWRD];     nl[mt][1] = Wl[rb + 8 * RWRD];
                    nh[mt][2] = Wh[rb + 4];            nl[mt][2] = Wl[rb + 4];
                    nh[mt][3] = Wh[rb + 8 * RWRD + 4]; nl[mt][3] = Wl[rb + 8 * RWRD + 4];
                }
            }
            int ky = tap / K, kx = tap - ky * K;
            int base = ((g + ky) * XW + kx + lr) * 12 + lq;
            #pragma unroll
            for (int nt = 0; nt < 5; nt++) {
                int off = base + nt * 96;   // 8 px * 12 words
                uint32_t bh0 = s_h[off], bh1 = s_h[off + 4];
                uint32_t bl0 = s_l[off], bl1 = s_l[off + 4];
                #pragma unroll
                for (int mt = 0; mt < 2; mt++) {
                    mma_bf16(acc[mt][nt], ah[mt], bh0, bh1);
                    mma_bf16(acc[mt][nt], ah[mt], bl0, bl1);
                    mma_bf16(acc[mt][nt], al[mt], bh0, bh1);
                }
            }
            if (tap + 1 < KK) {
                #pragma unroll
                for (int mt = 0; mt < 2; mt++)
                    #pragma unroll
                    for (int k = 0; k < 4; k++) { ah[mt][k] = nh[mt][k]; al[mt][k] = nl[mt][k]; }
            }
        }
    }

    int rr = y0 + g;
    #pragma unroll
    for (int mt = 0; mt < 2; mt++) {
        int co0 = coB + mt * 16 + lr;
        float b0 = bias[co0];
        float b8 = bias[co0 + 8];
        #pragma unroll
        for (int nt = 0; nt < 5; nt++) {
            int xb = x0 + nt * 8 + 2 * lq;
            #pragma unroll
            for (int e = 0; e < 2; e++) {
                int x = xb + e;
                if (x >= 100) continue;
                int px = rr * 100 + x;
                float v0 = acc[mt][nt][e] + b0;
                float v8 = acc[mt][nt][2 + e] + b8;
                if (RES == 1) {
                    v0 += resid[(long)px * CO + co0];
                    v8 += resid[(long)px * CO + co0 + 8];
                } else if (RES == 2) {
                    v0 += resid[(long)co0 * HW + px];
                    v8 += resid[(long)(co0 + 8) * HW + px];
                }
                if (ACT == 1) { v0 = gelu_exact(v0); v8 = gelu_exact(v8); }
                if (WF) {
                    outf[(long)px * CO + co0] = v0;
                    outf[(long)px * CO + co0 + 8] = v8;
                }
                if (WS) {
                    long pp = (long)((rr + 2) * PW + x + 2) * CO;
                    unsigned short h, l;
                    split_bf16(v0, h, l); oh[pp + co0] = h; ol[pp + co0] = l;
                    split_bf16(v8, h, l); oh[pp + co0 + 8] = h; ol[pp + co0 + 8] = l;
                }
            }
        }
    }
}

// ---- instance norm (channel-last C=128) ----
__global__ void inorm_part_kernel(const float* __restrict__ in, float* __restrict__ part) {
    int blk = blockIdx.x;
    int tid = threadIdx.x;
    int c = tid & 127;
    int sub = tid >> 7;
    float s = 0.f, s2 = 0.f;
    for (int px = blk * 100 + sub; px < blk * 100 + 100; px += 2) {
        float v = in[(long)px * 128 + c];
        s += v;
        s2 = fmaf(v, v, s2);
    }
    __shared__ float sh1[256], sh2[256];
    sh1[tid] = s; sh2[tid] = s2;
    __syncthreads();
    if (tid < 128) {
        part[blk * 256 + tid] = sh1[tid] + sh1[tid + 128];
        part[blk * 256 + 128 + tid] = sh2[tid] + sh2[tid + 128];
    }
}
__global__ void inorm_final_kernel(const float* __restrict__ part, float* __restrict__ mv) {
    int tid = threadIdx.x;
    float s = 0.f;
    for (int b = 0; b < 100; b++) s += part[b * 256 + tid];
    __shared__ float sh[256];
    sh[tid] = s;
    __syncthreads();
    if (tid < 128) {
        float m = sh[tid] * 1e-4f;
        float v = sh[tid + 128] * 1e-4f - m * m;
        mv[tid] = m;
        mv[128 + tid] = rsqrtf(v + 1e-5f);
    }
}
// MODE 0: fp32 channel-last. MODE 1: fp32 channel-major. MODE 2: fp32 CL + split padded.
template<int MODE>
__global__ void inorm_apply_kernel(const float* __restrict__ in, const float* __restrict__ mv,
                                   float* __restrict__ out,
                                   unsigned short* __restrict__ oh, unsigned short* __restrict__ ol) {
    int px = blockIdx.x;
    int c = threadIdx.x;
    float v = (in[(long)px * 128 + c] - mv[c]) * mv[128 + c];
    if (MODE == 1) out[(long)c * HW + px] = v;
    else out[(long)px * 128 + c] = v;
    if (MODE == 2) {
        int ppx = (px / 100 + 2) * PW + (px % 100) + 2;
        unsigned short h, l;
        split_bf16(v, h, l);
        oh[(long)ppx * 128 + c] = h;
        ol[(long)ppx * 128 + c] = l;
    }
}

__global__ void offsw_kernel(const float* __restrict__ q, const float* __restrict__ off_w,
                             const float* __restrict__ off_b, const float* __restrict__ sw_w,
                             const float* __restrict__ sw_b, const float* __restrict__ bev_pos,
                             float* __restrict__ ref_out, float* __restrict__ sw_out) {
    int pix = blockIdx.x;
    int tid = threadIdx.x;
    __shared__ float qv[128];
    __shared__ float logit[56];
    for (int c = tid; c < 128; c += 64) qv[c] = q[(long)pix * 128 + c];
    __syncthreads();
    if (tid < 24) {
        float s = off_b[tid];
        const float* wr = off_w + tid * 128;
        for (int c = 0; c < 128; c++) s = fmaf(qv[c], wr[c], s);
        logit[tid] = s;
    } else if (tid < 56) {
        int j = tid - 24;
        float s = sw_b[j];
        const float* wr = sw_w + j * 128;
        for (int c = 0; c < 128; c++) s = fmaf(qv[c], wr[c], s);
        logit[tid] = s;
    }
    __syncthreads();
    if (tid < 8) {
        int p = tid;
        const float lo[3] = {-50.f, -50.f, -5.f};
        const float span[3] = {100.f, 100.f, 8.f};
        const float rng = 0.25f + 1e-6f;
        const float zr = 4.0f + 1e-6f;
        #pragma unroll
        for (int d = 0; d < 3; d++) {
            float o = logit[p * 3 + d];
            float s = 1.0f / (1.0f + expf(-o));
            float off = (d < 2) ? (s * rng * 2.0f - rng) : (s * zr * 2.0f - zr);
            ref_out[pix * 24 + p * 3 + d] = bev_pos[pix * 3 + d] * span[d] + lo[d] + off;
        }
        float l0 = logit[24 + p * 4 + 0], l1 = logit[24 + p * 4 + 1];
        float l2 = logit[24 + p * 4 + 2], l3 = logit[24 + p * 4 + 3];
        float mx = fmaxf(fmaxf(l0, l1), fmaxf(l2, l3));
        float e0 = expf(l0 - mx), e1 = expf(l1 - mx);
        float e2 = expf(l2 - mx), e3 = expf(l3 - mx);
        float inv = 1.0f / (e0 + e1 + e2 + e3);
        sw_out[pix * 32 + p * 4 + 0] = e0 * inv;
        sw_out[pix * 32 + p * 4 + 1] = e1 * inv;
        sw_out[pix * 32 + p * 4 + 2] = e2 * inv;
        sw_out[pix * 32 + p * 4 + 3] = e3 * inv;
    }
}

__global__ void sample_kernel(const float* __restrict__ featT, const float* __restrict__ ref,
                              const float* __restrict__ swl, const float* __restrict__ lidar2img,
                              unsigned short* __restrict__ sfh, unsigned short* __restrict__ sfl) {
    int pix = blockIdx.x;
    int tid = threadIdx.x;
    __shared__ float Mm[96];
    __shared__ float refs[24];
    __shared__ float sws[32];
    __shared__ float pos3d[3];
    if (tid < 96) Mm[tid] = lidar2img[tid];
    if (tid < 24) refs[tid] = ref[pix * 24 + tid];
    if (tid < 32) sws[tid] = swl[pix * 32 + tid];
    __syncthreads();

    const int LH[4] = {32, 16, 8, 4};
    const int LW[4] = {88, 44, 22, 11};
    const int LOFF[4] = {L0_OFF, L1_OFF, L2_OFF, L3_OFF};

    float sfeat = 0.f, sweight = 0.f;
    for (int p = 0; p < 8; p++) {
        float acc = 0.f, acc3 = 0.f;
        float rx = refs[p * 3 + 0], ry = refs[p * 3 + 1], rz = refs[p * 3 + 2];
        for (int n = 0; n < 6; n++) {
            const float* M = Mm + n * 16;
            float cz = M[8] * rx + M[9] * ry + M[10] * rz + M[11];
            if (cz <= 1e-5f) continue;
            float cx = (M[0] * rx + M[1] * ry + M[2] * rz + M[3]) / cz;
            float cy = (M[4] * rx + M[5] * ry + M[6] * rz + M[7]) / cz;
            float gx = cx / 704.0f * 2.0f - 1.0f;
            float gy = cy / 256.0f * 2.0f - 1.0f;
            #pragma unroll
            for (int l = 0; l < 4; l++) {
                float wl = sws[p * 4 + l];
                float fx = (gx + 1.0f) * 0.5f * LW[l] - 0.5f;
                float fy = (gy + 1.0f) * 0.5f * LH[l] - 0.5f;
                float x0f = floorf(fx), y0f = floorf(fy);
                float wx = fx - x0f, wy = fy - y0f;
                int ix = (int)x0f, iy = (int)y0f;
                float w00 = (1.f - wx) * (1.f - wy) * wl;
                float w10 = wx * (1.f - wy) * wl;
                float w01 = (1.f - wx) * wy * wl;
                float w11 = wx * wy * wl;
                #pragma unroll
                for (int t = 0; t < 4; t++) {
                    int xi = ix + (t & 1);
                    int yi = iy + (t >> 1);
                    float cw = (t == 0) ? w00 : (t == 1) ? w10 : (t == 2) ? w01 : w11;
                    if (xi >= 0 && xi < LW[l] && yi >= 0 && yi < LH[l]) {
                        const float* fp = featT + LOFF[l] + ((long)(n * LH[l] + yi) * LW[l] + xi) * 132;
                        acc = fmaf(cw, fp[tid], acc);
                        if (tid < 3) acc3 = fmaf(cw, fp[128 + tid], acc3);
                    }
                }
            }
        }
        if (tid < 3) pos3d[tid] = acc3;
        __syncthreads();
        float dx = rx - pos3d[0], dy = ry - pos3d[1], dz = rz - pos3d[2];
        float wgt = expf(-0.1f * (dx * dx + dy * dy + dz * dz));
        sfeat += acc;
        sweight += acc * wgt;
        __syncthreads();
    }
    int ppx = (pix / 100 + 2) * PW + (pix % 100) + 2;
    unsigned short h, l;
    split_bf16(sfeat, h, l);
    sfh[(long)ppx * 256 + tid] = h;
    sfl[(long)ppx * 256 + tid] = l;
    split_bf16(sweight, h, l);
    sfh[(long)ppx * 256 + 128 + tid] = h;
    sfl[(long)ppx * 256 + 128 + tid] = l;
}

extern "C" void kernel_launch(void* const* d_in, const int* in_sizes, int n_in,
                              void* d_out, int out_size) {
    const float* bev_query = (const float*)d_in[0];
    const float* bev_pos   = (const float*)d_in[1];
    const float* lidar2img = (const float*)d_in[2];
    const float* feat0 = (const float*)d_in[3];
    const float* feat1 = (const float*)d_in[4];
    const float* feat2 = (const float*)d_in[5];
    const float* feat3 = (const float*)d_in[6];
    const float* in_w  = (const float*)d_in[7];
    const float* in_b  = (const float*)d_in[8];
    const float* off_w = (const float*)d_in[9];
    const float* off_b = (const float*)d_in[10];
    const float* sw_w  = (const float*)d_in[11];
    const float* sw_b  = (const float*)d_in[12];
    const float* mid_w1 = (const float*)d_in[13];
    const float* mid_b1 = (const float*)d_in[14];
    const float* mid_w2 = (const float*)d_in[15];
    const float* mid_b2 = (const float*)d_in[16];
    const float* mid_w3 = (const float*)d_in[17];
    const float* mid_b3 = (const float*)d_in[18];
    const float* out_w = (const float*)d_in[19];
    const float* out_b = (const float*)d_in[20];
    float* out = (float*)d_out;

    float *buf, *q, *q2, *refp, *swp, *featT, *part, *mv;
    cudaGetSymbolAddress((void**)&buf, g_buf);
    cudaGetSymbolAddress((void**)&q, g_q);
    cudaGetSymbolAddress((void**)&q2, g_q2);
    cudaGetSymbolAddress((void**)&refp, g_ref);
    cudaGetSymbolAddress((void**)&swp, g_swl);
    cudaGetSymbolAddress((void**)&featT, g_featT);
    cudaGetSymbolAddress((void**)&part, g_part);
    cudaGetSymbolAddress((void**)&mv, g_mv);

    unsigned short *bqph,*bqpl,*sfph,*sfpl,*m1ph,*m1pl,*m2ph,*m2pl,*q2ph,*q2pl;
    unsigned short *w1h,*w1l,*w2h,*w2l,*w3h,*w3l,*w4h,*w4l,*w5h,*w5l;
    cudaGetSymbolAddress((void**)&bqph, g_bqp_h); cudaGetSymbolAddress((void**)&bqpl, g_bqp_l);
    cudaGetSymbolAddress((void**)&sfph, g_sfp_h); cudaGetSymbolAddress((void**)&sfpl, g_sfp_l);
    cudaGetSymbolAddress((void**)&m1ph, g_m1p_h); cudaGetSymbolAddress((void**)&m1pl, g_m1p_l);
    cudaGetSymbolAddress((void**)&m2ph, g_m2p_h); cudaGetSymbolAddress((void**)&m2pl, g_m2p_l);
    cudaGetSymbolAddress((void**)&q2ph, g_q2p_h); cudaGetSymbolAddress((void**)&q2pl, g_q2p_l);
    cudaGetSymbolAddress((void**)&w1h, g_w1_h); cudaGetSymbolAddress((void**)&w1l, g_w1_l);
    cudaGetSymbolAddress((void**)&w2h, g_w2_h); cudaGetSymbolAddress((void**)&w2l, g_w2_l);
    cudaGetSymbolAddress((void**)&w3h, g_w3_h); cudaGetSymbolAddress((void**)&w3l, g_w3_l);
    cudaGetSymbolAddress((void**)&w4h, g_w4_h); cudaGetSymbolAddress((void**)&w4l, g_w4_l);
    cudaGetSymbolAddress((void**)&w5h, g_w5_h); cudaGetSymbolAddress((void**)&w5l, g_w5_l);

    wprep_all<<<(2850816 + 255) / 256, 256>>>(in_w, mid_w1, mid_w2, mid_w3, out_w,
                                              w1h, w1l, w2h, w2l, w3h, w3l, w4h, w4l, w5h, w5l);
    padsplit_cm_kernel<<<PPX, 128>>>(bev_query, bqph, bqpl);
    transpose_all<<<(2962080 + 255) / 256, 256>>>(feat0, feat1, feat2, feat3, featT);

    // stage1: conv5x5 + resid(bev_query, channel-major) -> buf; inorm -> q
    conv_mma_kernel<128,128,5,2,0,2,1,0><<<dim3(150,1), 256>>>(
        bqph, bqpl, w1h, w1l, in_b, bev_query, buf, nullptr, nullptr);
    inorm_part_kernel<<<100, 256>>>(buf, part);
    inorm_final_kernel<<<1, 256>>>(part, mv);
    inorm_apply_kernel<0><<<HW, 128>>>(buf, mv, q, nullptr, nullptr);

    offsw_kernel<<<HW, 64>>>(q, off_w, off_b, sw_w, sw_b, bev_pos, refp, swp);
    sample_kernel<<<HW, 128>>>(featT, refp, swp, lidar2img, sfph, sfpl);

    conv_mma_kernel<256,512,3,1,1,0,0,1><<<dim3(150,4), 256>>>(
        sfph, sfpl, w2h, w2l, mid_b1, nullptr, nullptr, m1ph, m1pl);
    conv_mma_kernel<512,512,1,0,1,0,0,1><<<dim3(150,4), 256>>>(
        m1ph, m1pl, w3h, w3l, mid_b2, nullptr, nullptr, m2ph, m2pl);
    conv_mma_kernel<512,128,3,1,0,1,1,0><<<dim3(150,1), 256>>>(
        m2ph, m2pl, w4h, w4l, mid_b3, q, buf, nullptr, nullptr);
    inorm_part_kernel<<<100, 256>>>(buf, part);
    inorm_final_kernel<<<1, 256>>>(part, mv);
    inorm_apply_kernel<2><<<HW, 128>>>(buf, mv, q2, q2ph, q2pl);

    conv_mma_kernel<128,128,5,2,0,1,1,0><<<dim3(150,1), 256>>>(
        q2ph, q2pl, w5h, w5l, out_b, q2, buf, nullptr, nullptr);
    inorm_part_kernel<<<100, 256>>>(buf, part);
    inorm_final_kernel<<<1, 256>>>(part, mv);
    inorm_apply_kernel<1><<<HW, 128>>>(buf, mv, out, nullptr, nullptr);
}

// round 8
// speedup vs baseline: 1.2621x; 1.2621x over previous
#include <cuda_runtime.h>
#include <cuda_bf16.h>
#include <math.h>
#include <stdint.h>

#define HW 10000
#define PW 104
#define PPX (PW*PW)

__device__ float g_buf[1280000];
__device__ float g_q[1280000];
__device__ float g_q2[1280000];
__device__ float g_ref[240000];
__device__ float g_swl[320000];
__device__ float g_featT[2962080];
__device__ float g_part[51200];
__device__ float g_mv[256];

__device__ unsigned short g_bqp_h[PPX*128], g_bqp_l[PPX*128];
__device__ unsigned short g_sfp_h[PPX*256], g_sfp_l[PPX*256];
__device__ unsigned short g_m1p_h[PPX*512], g_m1p_l[PPX*512];
__device__ unsigned short g_m2p_h[PPX*512], g_m2p_l[PPX*512];
__device__ unsigned short g_q2p_h[PPX*128], g_q2p_l[PPX*128];

// packed A-frag weights: [tap][ci_chunk][co32grp][lane][4 x uint4]
__device__ uint4 g_wp1[102400];   // 25*8*4*128
__device__ uint4 g_wp2[294912];   // 9*16*16*128
__device__ uint4 g_wp3[65536];    // 1*32*16*128
__device__ uint4 g_wp4[147456];   // 9*32*4*128
__device__ uint4 g_wp5[102400];

#define L0_OFF 0
#define L1_OFF 2230272
#define L2_OFF 2787840
#define L3_OFF 2927232

__device__ __forceinline__ float gelu_exact(float x) {
    return 0.5f * x * (1.0f + erff(x * 0.7071067811865475f));
}
__device__ __forceinline__ void split_bf16(float v, unsigned short& h, unsigned short& l) {
    __nv_bfloat16 bh = __float2bfloat16(v);
    float r = v - __bfloat162float(bh);
    __nv_bfloat16 bl = __float2bfloat16(r);
    h = __bfloat16_as_ushort(bh);
    l = __bfloat16_as_ushort(bl);
}
__device__ __forceinline__ void mma_bf16(float* c, const uint32_t* a, uint32_t b0, uint32_t b1) {
    asm volatile(
        "mma.sync.aligned.m16n8k16.row.col.f32.bf16.bf16.f32 "
        "{%0,%1,%2,%3}, {%4,%5,%6,%7}, {%8,%9}, {%0,%1,%2,%3};"
        : "+f"(c[0]), "+f"(c[1]), "+f"(c[2]), "+f"(c[3])
        : "r"(a[0]), "r"(a[1]), "r"(a[2]), "r"(a[3]), "r"(b0), "r"(b1));
}

// pack one uint4 of A-frag weights. idx decodes (t, ch, cg, lane, j).
__device__ __forceinline__ void wpack_one(const float* __restrict__ W, uint4* __restrict__ dst,
                                          int CO, int CIN, int KK, int idx) {
    int j = idx & 3;
    int lane = (idx >> 2) & 31;
    int rest = idx >> 7;
    int CG = CO >> 5, CH = CIN >> 4;
    int cg = rest % CG; rest /= CG;
    int ch = rest % CH;
    int t = rest / CH;
    int mt = j >> 1, lo = j & 1;
    int lr = lane >> 2, lq = lane & 3;
    int co = cg * 32 + mt * 16 + lr;
    int ci = ch * 16 + 2 * lq;
    unsigned int w[4];
    #pragma unroll
    for (int a = 0; a < 4; a++) {
        int cc = co + (a & 1) * 8;
        int kk = ci + (a >> 1) * 8;
        unsigned short h0, l0, h1, l1;
        split_bf16(W[((long)cc * CIN + kk) * KK + t], h0, l0);
        split_bf16(W[((long)cc * CIN + kk + 1) * KK + t], h1, l1);
        unsigned short x0 = lo ? l0 : h0, x1 = lo ? l1 : h1;
        w[a] = (unsigned int)x0 | ((unsigned int)x1 << 16);
    }
    dst[idx] = make_uint4(w[0], w[1], w[2], w[3]);
}

__global__ void wprep_all(const float* __restrict__ w1, const float* __restrict__ w2,
                          const float* __restrict__ w3, const float* __restrict__ w4,
                          const float* __restrict__ w5,
                          uint4* p1, uint4* p2, uint4* p3, uint4* p4, uint4* p5) {
    const int N1 = 102400, N2 = 294912, N3 = 65536, N4 = 147456, N5 = 102400;
    int idx = blockIdx.x * blockDim.x + threadIdx.x;
    if (idx < N1) wpack_one(w1, p1, 128, 128, 25, idx);
    else if (idx < N1+N2) wpack_one(w2, p2, 512, 256, 9, idx - N1);
    else if (idx < N1+N2+N3) wpack_one(w3, p3, 512, 512, 1, idx - N1 - N2);
    else if (idx < N1+N2+N3+N4) wpack_one(w4, p4, 128, 512, 9, idx - N1 - N2 - N3);
    else if (idx < N1+N2+N3+N4+N5) wpack_one(w5, p5, 128, 128, 25, idx - N1 - N2 - N3 - N4);
}

__global__ void padsplit_cm_kernel(const float* __restrict__ src,
                                   unsigned short* __restrict__ dh, unsigned short* __restrict__ dl) {
    int ppx = blockIdx.x;
    int c = threadIdx.x;
    int py = ppx / PW, px = ppx % PW;
    int y = py - 2, x = px - 2;
    float v = 0.0f;
    if (y >= 0 && y < 100 && x >= 0 && x < 100) v = src[c * HW + y * 100 + x];
    unsigned short h, l;
    split_bf16(v, h, l);
    dh[(long)ppx * 128 + c] = h;
    dl[(long)ppx * 128 + c] = l;
}

__device__ __forceinline__ void tpose_one(const float* src, float* dst, int Hl, int Wl, int idx) {
    int hw = Hl * Wl;
    int n = idx / (132 * hw);
    int r = idx - n * 132 * hw;
    int c = r / hw;
    int p = r - c * hw;
    dst[(n * hw + p) * 132 + c] = src[idx];
}

__global__ void transpose_all(const float* __restrict__ f0, const float* __restrict__ f1,
                              const float* __restrict__ f2, const float* __restrict__ f3,
                              float* __restrict__ featT) {
    const int T0 = 2230272, T1 = 557568, T2 = 139392, T3 = 34848;
    int idx = blockIdx.x * blockDim.x + threadIdx.x;
    if (idx < T0) tpose_one(f0, featT + L0_OFF, 32, 88, idx);
    else if (idx < T0 + T1) tpose_one(f1, featT + L1_OFF, 16, 44, idx - T0);
    else if (idx < T0 + T1 + T2) tpose_one(f2, featT + L2_OFF, 8, 22, idx - T0 - T1);
    else if (idx < T0 + T1 + T2 + T3) tpose_one(f3, featT + L3_OFF, 4, 11, idx - T0 - T1 - T2);
}

// implicit-GEMM conv: 256 thr = 8 warps = 4 co-groups x 2 row-groups.
// Block tile 128co x (2 rows x 40 px); warp 32co x 1 row x 40px (5 ntiles).
// A: packed uint4 frags (4 LDG.128/tap). B: hi/lo-interleaved smem (1 LDS.128/tap-ntile).
template<int CIN, int CO, int K, int PAD, int ACT, int RES, int WF, int WS>
__global__ void __launch_bounds__(256)
conv_mma_kernel(const unsigned short* __restrict__ inp_h, const unsigned short* __restrict__ inp_l,
                const uint4* __restrict__ Wp,
                const float* __restrict__ bias, const float* __restrict__ resid,
                float* __restrict__ outf,
                unsigned short* __restrict__ oh, unsigned short* __restrict__ ol) {
    constexpr int KK = K * K;
    constexpr int XW = (40 + (K - 1)) | 1;
    constexpr int RWS = 2 + (K - 1);
    constexpr int NPX = RWS * XW;
    constexpr int PA = 2 - PAD;
    constexpr int CG = CO >> 5;
    constexpr int CH = CIN >> 4;

    __shared__ uint32_t s_b[NPX * 16];

    int tid = threadIdx.x;
    int warp = tid >> 5;
    int g = warp >> 2;
    int lane = tid & 31;
    int lq = lane & 3;
    int lr = lane >> 2;

    int nb = blockIdx.x;
    int y0 = (nb / 3) * 2;
    int x0 = (nb % 3) * 40;
    int cg = blockIdx.y * 4 + (warp & 3);
    int coB = cg * 32;

    float acc[2][5][4];
    #pragma unroll
    for (int m = 0; m < 2; m++)
        #pragma unroll
        for (int n = 0; n < 5; n++) {
            acc[m][n][0] = 0.f; acc[m][n][1] = 0.f; acc[m][n][2] = 0.f; acc[m][n][3] = 0.f;
        }

    uint32_t af[16], nf[16];

    for (int ch = 0; ch < CH; ch++) {
        int ci0 = ch * 16;
        __syncthreads();
        for (int p = tid; p < NPX; p += 256) {
            int r = p / XW;
            int xx = p - r * XW;
            int prow = y0 + r + PA;
            int pcol = x0 + xx + PA;
            uint4 vh0, vh1, vl0, vl1;
            if (pcol < PW) {
                const uint4* gh = (const uint4*)(inp_h + ((long)(prow * PW + pcol) * CIN + ci0));
                const uint4* gl = (const uint4*)(inp_l + ((long)(prow * PW + pcol) * CIN + ci0));
                vh0 = gh[0]; vh1 = gh[1]; vl0 = gl[0]; vl1 = gl[1];
            } else {
                vh0 = make_uint4(0,0,0,0); vh1 = vh0; vl0 = vh0; vl1 = vh0;
            }
            uint4* sp = (uint4*)(s_b + p * 16);
            sp[0] = make_uint4(vh0.x, vh1.x, vl0.x, vl1.x);
            sp[1] = make_uint4(vh0.y, vh1.y, vl0.y, vl1.y);
            sp[2] = make_uint4(vh0.z, vh1.z, vl0.z, vl1.z);
            sp[3] = make_uint4(vh0.w, vh1.w, vl0.w, vl1.w);
        }
        __syncthreads();

        long ib = (((long)0 * CH + ch) * CG + cg) * 128 + lane * 4;
        *(uint4*)(af + 0)  = Wp[ib + 0];
        *(uint4*)(af + 4)  = Wp[ib + 1];
        *(uint4*)(af + 8)  = Wp[ib + 2];
        *(uint4*)(af + 12) = Wp[ib + 3];

        #pragma unroll 1
        for (int tap = 0; tap < KK; tap++) {
            if (tap + 1 < KK) {
                long nbx = (((long)(tap + 1) * CH + ch) * CG + cg) * 128 + lane * 4;
                *(uint4*)(nf + 0)  = Wp[nbx + 0];
                *(uint4*)(nf + 4)  = Wp[nbx + 1];
                *(uint4*)(nf + 8)  = Wp[nbx + 2];
                *(uint4*)(nf + 12) = Wp[nbx + 3];
            }
            int ky = tap / K, kx = tap - ky * K;
            int base = ((g + ky) * XW + kx + lr) * 16 + lq * 4;
            #pragma unroll
            for (int nt = 0; nt < 5; nt++) {
                uint4 b = *(const uint4*)(s_b + base + nt * 128);
                mma_bf16(acc[0][nt], af + 0, b.x, b.y);   // Ah*Bh (mt0)
                mma_bf16(acc[0][nt], af + 0, b.z, b.w);   // Ah*Bl
                mma_bf16(acc[0][nt], af + 4, b.x, b.y);   // Al*Bh
                mma_bf16(acc[1][nt], af + 8, b.x, b.y);
                mma_bf16(acc[1][nt], af + 8, b.z, b.w);
                mma_bf16(acc[1][nt], af + 12, b.x, b.y);
            }
            if (tap + 1 < KK) {
                #pragma unroll
                for (int k = 0; k < 16; k++) af[k] = nf[k];
            }
        }
    }

    int rr = y0 + g;
    #pragma unroll
    for (int mt = 0; mt < 2; mt++) {
        int co0 = coB + mt * 16 + lr;
        float b0 = bias[co0];
        float b8 = bias[co0 + 8];
        #pragma unroll
        for (int nt = 0; nt < 5; nt++) {
            int xb = x0 + nt * 8 + 2 * lq;
            #pragma unroll
            for (int e = 0; e < 2; e++) {
                int x = xb + e;
                if (x >= 100) continue;
                int px = rr * 100 + x;
                float v0 = acc[mt][nt][e] + b0;
                float v8 = acc[mt][nt][2 + e] + b8;
                if (RES == 1) {
                    v0 += resid[(long)px * CO + co0];
                    v8 += resid[(long)px * CO + co0 + 8];
                } else if (RES == 2) {
                    v0 += resid[(long)co0 * HW + px];
                    v8 += resid[(long)(co0 + 8) * HW + px];
                }
                if (ACT == 1) { v0 = gelu_exact(v0); v8 = gelu_exact(v8); }
                if (WF) {
                    outf[(long)px * CO + co0] = v0;
                    outf[(long)px * CO + co0 + 8] = v8;
                }
                if (WS) {
                    long pp = (long)((rr + 2) * PW + x + 2) * CO;
                    unsigned short h, l;
                    split_bf16(v0, h, l); oh[pp + co0] = h; ol[pp + co0] = l;
                    split_bf16(v8, h, l); oh[pp + co0 + 8] = h; ol[pp + co0 + 8] = l;
                }
            }
        }
    }
}

// ---- instance norm (channel-last C=128) ----
__global__ void inorm_part_kernel(const float* __restrict__ in, float* __restrict__ part) {
    int blk = blockIdx.x;
    int tid = threadIdx.x;
    int c = tid & 127;
    int sub = tid >> 7;
    float s = 0.f, s2 = 0.f;
    for (int px = blk * 100 + sub; px < blk * 100 + 100; px += 2) {
        float v = in[(long)px * 128 + c];
        s += v;
        s2 = fmaf(v, v, s2);
    }
    __shared__ float sh1[256], sh2[256];
    sh1[tid] = s; sh2[tid] = s2;
    __syncthreads();
    if (tid < 128) {
        part[blk * 256 + tid] = sh1[tid] + sh1[tid + 128];
        part[blk * 256 + 128 + tid] = sh2[tid] + sh2[tid + 128];
    }
}
__global__ void inorm_final_kernel(const float* __restrict__ part, float* __restrict__ mv) {
    int tid = threadIdx.x;
    float s = 0.f;
    for (int b = 0; b < 100; b++) s += part[b * 256 + tid];
    __shared__ float sh[256];
    sh[tid] = s;
    __syncthreads();
    if (tid < 128) {
        float m = sh[tid] * 1e-4f;
        float v = sh[tid + 128] * 1e-4f - m * m;
        mv[tid] = m;
        mv[128 + tid] = rsqrtf(v + 1e-5f);
    }
}
template<int MODE>
__global__ void inorm_apply_kernel(const float* __restrict__ in, const float* __restrict__ mv,
                                   float* __restrict__ out,
                                   unsigned short* __restrict__ oh, unsigned short* __restrict__ ol) {
    int px = blockIdx.x;
    int c = threadIdx.x;
    float v = (in[(long)px * 128 + c] - mv[c]) * mv[128 + c];
    if (MODE == 1) out[(long)c * HW + px] = v;
    else out[(long)px * 128 + c] = v;
    if (MODE == 2) {
        int ppx = (px / 100 + 2) * PW + (px % 100) + 2;
        unsigned short h, l;
        split_bf16(v, h, l);
        oh[(long)ppx * 128 + c] = h;
        ol[(long)ppx * 128 + c] = l;
    }
}

__global__ void offsw_kernel(const float* __restrict__ q, const float* __restrict__ off_w,
                             const float* __restrict__ off_b, const float* __restrict__ sw_w,
                             const float* __restrict__ sw_b, const float* __restrict__ bev_pos,
                             float* __restrict__ ref_out, float* __restrict__ sw_out) {
    int pix = blockIdx.x;
    int tid = threadIdx.x;
    __shared__ float qv[128];
    __shared__ float logit[56];
    for (int c = tid; c < 128; c += 64) qv[c] = q[(long)pix * 128 + c];
    __syncthreads();
    if (tid < 24) {
        float s = off_b[tid];
        const float* wr = off_w + tid * 128;
        for (int c = 0; c < 128; c++) s = fmaf(qv[c], wr[c], s);
        logit[tid] = s;
    } else if (tid < 56) {
        int j = tid - 24;
        float s = sw_b[j];
        const float* wr = sw_w + j * 128;
        for (int c = 0; c < 128; c++) s = fmaf(qv[c], wr[c], s);
        logit[tid] = s;
    }
    __syncthreads();
    if (tid < 8) {
        int p = tid;
        const float lo[3] = {-50.f, -50.f, -5.f};
        const float span[3] = {100.f, 100.f, 8.f};
        const float rng = 0.25f + 1e-6f;
        const float zr = 4.0f + 1e-6f;
        #pragma unroll
        for (int d = 0; d < 3; d++) {
            float o = logit[p * 3 + d];
            float s = 1.0f / (1.0f + expf(-o));
            float off = (d < 2) ? (s * rng * 2.0f - rng) : (s * zr * 2.0f - zr);
            ref_out[pix * 24 + p * 3 + d] = bev_pos[pix * 3 + d] * span[d] + lo[d] + off;
        }
        float l0 = logit[24 + p * 4 + 0], l1 = logit[24 + p * 4 + 1];
        float l2 = logit[24 + p * 4 + 2], l3 = logit[24 + p * 4 + 3];
        float mx = fmaxf(fmaxf(l0, l1), fmaxf(l2, l3));
        float e0 = expf(l0 - mx), e1 = expf(l1 - mx);
        float e2 = expf(l2 - mx), e3 = expf(l3 - mx);
        float inv = 1.0f / (e0 + e1 + e2 + e3);
        sw_out[pix * 32 + p * 4 + 0] = e0 * inv;
        sw_out[pix * 32 + p * 4 + 1] = e1 * inv;
        sw_out[pix * 32 + p * 4 + 2] = e2 * inv;
        sw_out[pix * 32 + p * 4 + 3] = e3 * inv;
    }
}

__global__ void sample_kernel(const float* __restrict__ featT, const float* __restrict__ ref,
                              const float* __restrict__ swl, const float* __restrict__ lidar2img,
                              unsigned short* __restrict__ sfh, unsigned short* __restrict__ sfl) {
    int pix = blockIdx.x;
    int tid = threadIdx.x;
    __shared__ float Mm[96];
    __shared__ float refs[24];
    __shared__ float sws[32];
    __shared__ float pos3d[3];
    if (tid < 96) Mm[tid] = lidar2img[tid];
    if (tid < 24) refs[tid] = ref[pix * 24 + tid];
    if (tid < 32) sws[tid] = swl[pix * 32 + tid];
    __syncthreads();

    const int LH[4] = {32, 16, 8, 4};
    const int LW[4] = {88, 44, 22, 11};
    const int LOFF[4] = {L0_OFF, L1_OFF, L2_OFF, L3_OFF};

    float sfeat = 0.f, sweight = 0.f;
    for (int p = 0; p < 8; p++) {
        float acc = 0.f, acc3 = 0.f;
        float rx = refs[p * 3 + 0], ry = refs[p * 3 + 1], rz = refs[p * 3 + 2];
        for (int n = 0; n < 6; n++) {
            const float* M = Mm + n * 16;
            float cz = M[8] * rx + M[9] * ry + M[10] * rz + M[11];
            if (cz <= 1e-5f) continue;
            float cx = (M[0] * rx + M[1] * ry + M[2] * rz + M[3]) / cz;
            float cy = (M[4] * rx + M[5] * ry + M[6] * rz + M[7]) / cz;
            float gx = cx / 704.0f * 2.0f - 1.0f;
            float gy = cy / 256.0f * 2.0f - 1.0f;
            #pragma unroll
            for (int l = 0; l < 4; l++) {
                float wl = sws[p * 4 + l];
                float fx = (gx + 1.0f) * 0.5f * LW[l] - 0.5f;
                float fy = (gy + 1.0f) * 0.5f * LH[l] - 0.5f;
                float x0f = floorf(fx), y0f = floorf(fy);
                float wx = fx - x0f, wy = fy - y0f;
                int ix = (int)x0f, iy = (int)y0f;
                float w00 = (1.f - wx) * (1.f - wy) * wl;
                float w10 = wx * (1.f - wy) * wl;
                float w01 = (1.f - wx) * wy * wl;
                float w11 = wx * wy * wl;
                #pragma unroll
                for (int t = 0; t < 4; t++) {
                    int xi = ix + (t & 1);
                    int yi = iy + (t >> 1);
                    float cw = (t == 0) ? w00 : (t == 1) ? w10 : (t == 2) ? w01 : w11;
                    if (xi >= 0 && xi < LW[l] && yi >= 0 && yi < LH[l]) {
                        const float* fp = featT + LOFF[l] + ((long)(n * LH[l] + yi) * LW[l] + xi) * 132;
                        acc = fmaf(cw, fp[tid], acc);
                        if (tid < 3) acc3 = fmaf(cw, fp[128 + tid], acc3);
                    }
                }
            }
        }
        if (tid < 3) pos3d[tid] = acc3;
        __syncthreads();
        float dx = rx - pos3d[0], dy = ry - pos3d[1], dz = rz - pos3d[2];
        float wgt = expf(-0.1f * (dx * dx + dy * dy + dz * dz));
        sfeat += acc;
        sweight += acc * wgt;
        __syncthreads();
    }
    int ppx = (pix / 100 + 2) * PW + (pix % 100) + 2;
    unsigned short h, l;
    split_bf16(sfeat, h, l);
    sfh[(long)ppx * 256 + tid] = h;
    sfl[(long)ppx * 256 + tid] = l;
    split_bf16(sweight, h, l);
    sfh[(long)ppx * 256 + 128 + tid] = h;
    sfl[(long)ppx * 256 + 128 + tid] = l;
}

extern "C" void kernel_launch(void* const* d_in, const int* in_sizes, int n_in,
                              void* d_out, int out_size) {
    const float* bev_query = (const float*)d_in[0];
    const float* bev_pos   = (const float*)d_in[1];
    const float* lidar2img = (const float*)d_in[2];
    const float* feat0 = (const float*)d_in[3];
    const float* feat1 = (const float*)d_in[4];
    const float* feat2 = (const float*)d_in[5];
    const float* feat3 = (const float*)d_in[6];
    const float* in_w  = (const float*)d_in[7];
    const float* in_b  = (const float*)d_in[8];
    const float* off_w = (const float*)d_in[9];
    const float* off_b = (const float*)d_in[10];
    const float* sw_w  = (const float*)d_in[11];
    const float* sw_b  = (const float*)d_in[12];
    const float* mid_w1 = (const float*)d_in[13];
    const float* mid_b1 = (const float*)d_in[14];
    const float* mid_w2 = (const float*)d_in[15];
    const float* mid_b2 = (const float*)d_in[16];
    const float* mid_w3 = (const float*)d_in[17];
    const float* mid_b3 = (const float*)d_in[18];
    const float* out_w = (const float*)d_in[19];
    const float* out_b = (const float*)d_in[20];
    float* out = (float*)d_out;

    float *buf, *q, *q2, *refp, *swp, *featT, *part, *mv;
    cudaGetSymbolAddress((void**)&buf, g_buf);
    cudaGetSymbolAddress((void**)&q, g_q);
    cudaGetSymbolAddress((void**)&q2, g_q2);
    cudaGetSymbolAddress((void**)&refp, g_ref);
    cudaGetSymbolAddress((void**)&swp, g_swl);
    cudaGetSymbolAddress((void**)&featT, g_featT);
    cudaGetSymbolAddress((void**)&part, g_part);
    cudaGetSymbolAddress((void**)&mv, g_mv);

    unsigned short *bqph,*bqpl,*sfph,*sfpl,*m1ph,*m1pl,*m2ph,*m2pl,*q2ph,*q2pl;
    uint4 *p1,*p2,*p3,*p4,*p5;
    cudaGetSymbolAddress((void**)&bqph, g_bqp_h); cudaGetSymbolAddress((void**)&bqpl, g_bqp_l);
    cudaGetSymbolAddress((void**)&sfph, g_sfp_h); cudaGetSymbolAddress((void**)&sfpl, g_sfp_l);
    cudaGetSymbolAddress((void**)&m1ph, g_m1p_h); cudaGetSymbolAddress((void**)&m1pl, g_m1p_l);
    cudaGetSymbolAddress((void**)&m2ph, g_m2p_h); cudaGetSymbolAddress((void**)&m2pl, g_m2p_l);
    cudaGetSymbolAddress((void**)&q2ph, g_q2p_h); cudaGetSymbolAddress((void**)&q2pl, g_q2p_l);
    cudaGetSymbolAddress((void**)&p1, g_wp1);
    cudaGetSymbolAddress((void**)&p2, g_wp2);
    cudaGetSymbolAddress((void**)&p3, g_wp3);
    cudaGetSymbolAddress((void**)&p4, g_wp4);
    cudaGetSymbolAddress((void**)&p5, g_wp5);

    wprep_all<<<(712704 + 255) / 256, 256>>>(in_w, mid_w1, mid_w2, mid_w3, out_w,
                                             p1, p2, p3, p4, p5);
    padsplit_cm_kernel<<<PPX, 128>>>(bev_query, bqph, bqpl);
    transpose_all<<<(2962080 + 255) / 256, 256>>>(feat0, feat1, feat2, feat3, featT);

    conv_mma_kernel<128,128,5,2,0,2,1,0><<<dim3(150,1), 256>>>(
        bqph, bqpl, p1, in_b, bev_query, buf, nullptr, nullptr);
    inorm_part_kernel<<<100, 256>>>(buf, part);
    inorm_final_kernel<<<1, 256>>>(part, mv);
    inorm_apply_kernel<0><<<HW, 128>>>(buf, mv, q, nullptr, nullptr);

    offsw_kernel<<<HW, 64>>>(q, off_w, off_b, sw_w, sw_b, bev_pos, refp, swp);
    sample_kernel<<<HW, 128>>>(featT, refp, swp, lidar2img, sfph, sfpl);

    conv_mma_kernel<256,512,3,1,1,0,0,1><<<dim3(150,4), 256>>>(
        sfph, sfpl, p2, mid_b1, nullptr, nullptr, m1ph, m1pl);
    conv_mma_kernel<512,512,1,0,1,0,0,1><<<dim3(150,4), 256>>>(
        m1ph, m1pl, p3, mid_b2, nullptr, nullptr, m2ph, m2pl);
    conv_mma_kernel<512,128,3,1,0,1,1,0><<<dim3(150,1), 256>>>(
        m2ph, m2pl, p4, mid_b3, q, buf, nullptr, nullptr);
    inorm_part_kernel<<<100, 256>>>(buf, part);
    inorm_final_kernel<<<1, 256>>>(part, mv);
    inorm_apply_kernel<2><<<HW, 128>>>(buf, mv, q2, q2ph, q2pl);

    conv_mma_kernel<128,128,5,2,0,1,1,0><<<dim3(150,1), 256>>>(
        q2ph, q2pl, p5, out_b, q2, buf, nullptr, nullptr);
    inorm_part_kernel<<<100, 256>>>(buf, part);
    inorm_final_kernel<<<1, 256>>>(part, mv);
    inorm_apply_kernel<1><<<HW, 128>>>(buf, mv, out, nullptr, nullptr);
}

// round 9
// speedup vs baseline: 1.3517x; 1.0710x over previous
#include <cuda_runtime.h>
#include <cuda_bf16.h>
#include <math.h>
#include <stdint.h>

#define HW 10000
#define PW 104
#define PPX (PW*PW)

__device__ float g_buf[1280000];
__device__ float g_q[1280000];
__device__ float g_q2[1280000];
__device__ float g_ref[240000];
__device__ float g_swl[320000];
__device__ float g_featT[2962080];
__device__ float g_part[51200];
__device__ float g_mv[256];

__device__ unsigned short g_bqp_h[PPX*128], g_bqp_l[PPX*128];
__device__ unsigned short g_sfp_h[PPX*256], g_sfp_l[PPX*256];
__device__ unsigned short g_m1p_h[PPX*512], g_m1p_l[PPX*512];
__device__ unsigned short g_m2p_h[PPX*512], g_m2p_l[PPX*512];
__device__ unsigned short g_q2p_h[PPX*128], g_q2p_l[PPX*128];

// packed A-frag weights: [tap][ci_chunk][co32grp][lane][4 x uint4]
__device__ uint4 g_wp1[102400];
__device__ uint4 g_wp2[294912];
__device__ uint4 g_wp3[65536];
__device__ uint4 g_wp4[147456];
__device__ uint4 g_wp5[102400];

#define L0_OFF 0
#define L1_OFF 2230272
#define L2_OFF 2787840
#define L3_OFF 2927232

__device__ __forceinline__ float gelu_exact(float x) {
    return 0.5f * x * (1.0f + erff(x * 0.7071067811865475f));
}
__device__ __forceinline__ void split_bf16(float v, unsigned short& h, unsigned short& l) {
    __nv_bfloat16 bh = __float2bfloat16(v);
    float r = v - __bfloat162float(bh);
    __nv_bfloat16 bl = __float2bfloat16(r);
    h = __bfloat16_as_ushort(bh);
    l = __bfloat16_as_ushort(bl);
}
__device__ __forceinline__ void mma_bf16(float* c, const uint32_t* a, uint32_t b0, uint32_t b1) {
    asm volatile(
        "mma.sync.aligned.m16n8k16.row.col.f32.bf16.bf16.f32 "
        "{%0,%1,%2,%3}, {%4,%5,%6,%7}, {%8,%9}, {%0,%1,%2,%3};"
        : "+f"(c[0]), "+f"(c[1]), "+f"(c[2]), "+f"(c[3])
        : "r"(a[0]), "r"(a[1]), "r"(a[2]), "r"(a[3]), "r"(b0), "r"(b1));
}

__device__ __forceinline__ void wpack_one(const float* __restrict__ W, uint4* __restrict__ dst,
                                          int CO, int CIN, int KK, int idx) {
    int j = idx & 3;
    int lane = (idx >> 2) & 31;
    int rest = idx >> 7;
    int CG = CO >> 5, CH = CIN >> 4;
    int cg = rest % CG; rest /= CG;
    int ch = rest % CH;
    int t = rest / CH;
    int mt = j >> 1, lo = j & 1;
    int lr = lane >> 2, lq = lane & 3;
    int co = cg * 32 + mt * 16 + lr;
    int ci = ch * 16 + 2 * lq;
    unsigned int w[4];
    #pragma unroll
    for (int a = 0; a < 4; a++) {
        int cc = co + (a & 1) * 8;
        int kk = ci + (a >> 1) * 8;
        unsigned short h0, l0, h1, l1;
        split_bf16(W[((long)cc * CIN + kk) * KK + t], h0, l0);
        split_bf16(W[((long)cc * CIN + kk + 1) * KK + t], h1, l1);
        unsigned short x0 = lo ? l0 : h0, x1 = lo ? l1 : h1;
        w[a] = (unsigned int)x0 | ((unsigned int)x1 << 16);
    }
    dst[idx] = make_uint4(w[0], w[1], w[2], w[3]);
}

__global__ void wprep_all(const float* __restrict__ w1, const float* __restrict__ w2,
                          const float* __restrict__ w3, const float* __restrict__ w4,
                          const float* __restrict__ w5,
                          uint4* p1, uint4* p2, uint4* p3, uint4* p4, uint4* p5) {
    const int N1 = 102400, N2 = 294912, N3 = 65536, N4 = 147456, N5 = 102400;
    int idx = blockIdx.x * blockDim.x + threadIdx.x;
    if (idx < N1) wpack_one(w1, p1, 128, 128, 25, idx);
    else if (idx < N1+N2) wpack_one(w2, p2, 512, 256, 9, idx - N1);
    else if (idx < N1+N2+N3) wpack_one(w3, p3, 512, 512, 1, idx - N1 - N2);
    else if (idx < N1+N2+N3+N4) wpack_one(w4, p4, 128, 512, 9, idx - N1 - N2 - N3);
    else if (idx < N1+N2+N3+N4+N5) wpack_one(w5, p5, 128, 128, 25, idx - N1 - N2 - N3 - N4);
}

__global__ void padsplit_cm_kernel(const float* __restrict__ src,
                                   unsigned short* __restrict__ dh, unsigned short* __restrict__ dl) {
    int ppx = blockIdx.x;
    int c = threadIdx.x;
    int py = ppx / PW, px = ppx % PW;
    int y = py - 2, x = px - 2;
    float v = 0.0f;
    if (y >= 0 && y < 100 && x >= 0 && x < 100) v = src[c * HW + y * 100 + x];
    unsigned short h, l;
    split_bf16(v, h, l);
    dh[(long)ppx * 128 + c] = h;
    dl[(long)ppx * 128 + c] = l;
}

__device__ __forceinline__ void tpose_one(const float* src, float* dst, int Hl, int Wl, int idx) {
    int hw = Hl * Wl;
    int n = idx / (132 * hw);
    int r = idx - n * 132 * hw;
    int c = r / hw;
    int p = r - c * hw;
    dst[(n * hw + p) * 132 + c] = src[idx];
}

__global__ void transpose_all(const float* __restrict__ f0, const float* __restrict__ f1,
                              const float* __restrict__ f2, const float* __restrict__ f3,
                              float* __restrict__ featT) {
    const int T0 = 2230272, T1 = 557568, T2 = 139392, T3 = 34848;
    int idx = blockIdx.x * blockDim.x + threadIdx.x;
    if (idx < T0) tpose_one(f0, featT + L0_OFF, 32, 88, idx);
    else if (idx < T0 + T1) tpose_one(f1, featT + L1_OFF, 16, 44, idx - T0);
    else if (idx < T0 + T1 + T2) tpose_one(f2, featT + L2_OFF, 8, 22, idx - T0 - T1);
    else if (idx < T0 + T1 + T2 + T3) tpose_one(f3, featT + L3_OFF, 4, 11, idx - T0 - T1 - T2);
}

// implicit-GEMM conv. 256 thr = 8 warps = 4 co-groups x 2 row-groups.
// MMAs issued in 3 passes of 10 independent ops; A-frags ping-ponged (no copies).
template<int CIN, int CO, int K, int PAD, int ACT, int RES, int WF, int WS>
__global__ void __launch_bounds__(256, 2)
conv_mma_kernel(const unsigned short* __restrict__ inp_h, const unsigned short* __restrict__ inp_l,
                const uint4* __restrict__ Wp,
                const float* __restrict__ bias, const float* __restrict__ resid,
                float* __restrict__ outf,
                unsigned short* __restrict__ oh, unsigned short* __restrict__ ol) {
    constexpr int KK = K * K;
    constexpr int XW = (40 + (K - 1)) | 1;
    constexpr int RWS = 2 + (K - 1);
    constexpr int NPX = RWS * XW;
    constexpr int PA = 2 - PAD;
    constexpr int CG = CO >> 5;
    constexpr int CH = CIN >> 4;

    __shared__ uint32_t s_b[NPX * 16];

    int tid = threadIdx.x;
    int warp = tid >> 5;
    int g = warp >> 2;
    int lane = tid & 31;
    int lq = lane & 3;
    int lr = lane >> 2;

    int nb = blockIdx.x;
    int y0 = (nb / 3) * 2;
    int x0 = (nb % 3) * 40;
    int cg = blockIdx.y * 4 + (warp & 3);
    int coB = cg * 32;

    float acc[2][5][4];
    #pragma unroll
    for (int m = 0; m < 2; m++)
        #pragma unroll
        for (int n = 0; n < 5; n++) {
            acc[m][n][0] = 0.f; acc[m][n][1] = 0.f; acc[m][n][2] = 0.f; acc[m][n][3] = 0.f;
        }

    uint32_t F0[16], F1[16];
    int chv = 0;

    auto load_frag = [&](uint32_t* F, int tap) {
        long ib = (((long)tap * CH + chv) * CG + cg) * 128 + lane * 4;
        *(uint4*)(F + 0)  = Wp[ib + 0];
        *(uint4*)(F + 4)  = Wp[ib + 1];
        *(uint4*)(F + 8)  = Wp[ib + 2];
        *(uint4*)(F + 12) = Wp[ib + 3];
    };
    auto compute_tap = [&](const uint32_t* F, int tap) {
        int ky = tap / K, kx = tap - ky * K;
        int base = ((g + ky) * XW + kx + lr) * 16 + lq * 4;
        uint4 b[5];
        #pragma unroll
        for (int nt = 0; nt < 5; nt++) b[nt] = *(const uint4*)(s_b + base + nt * 128);
        #pragma unroll
        for (int nt = 0; nt < 5; nt++) {
            mma_bf16(acc[0][nt], F + 0, b[nt].x, b[nt].y);
            mma_bf16(acc[1][nt], F + 8, b[nt].x, b[nt].y);
        }
        #pragma unroll
        for (int nt = 0; nt < 5; nt++) {
            mma_bf16(acc[0][nt], F + 0, b[nt].z, b[nt].w);
            mma_bf16(acc[1][nt], F + 8, b[nt].z, b[nt].w);
        }
        #pragma unroll
        for (int nt = 0; nt < 5; nt++) {
            mma_bf16(acc[0][nt], F + 4, b[nt].x, b[nt].y);
            mma_bf16(acc[1][nt], F + 12, b[nt].x, b[nt].y);
        }
    };

    for (int ch = 0; ch < CH; ch++) {
        chv = ch;
        int ci0 = ch * 16;
        __syncthreads();
        for (int p = tid; p < NPX; p += 256) {
            int r = p / XW;
            int xx = p - r * XW;
            int prow = y0 + r + PA;
            int pcol = x0 + xx + PA;
            uint4 vh0, vh1, vl0, vl1;
            if (pcol < PW) {
                const uint4* gh = (const uint4*)(inp_h + ((long)(prow * PW + pcol) * CIN + ci0));
                const uint4* gl = (const uint4*)(inp_l + ((long)(prow * PW + pcol) * CIN + ci0));
                vh0 = gh[0]; vh1 = gh[1]; vl0 = gl[0]; vl1 = gl[1];
            } else {
                vh0 = make_uint4(0,0,0,0); vh1 = vh0; vl0 = vh0; vl1 = vh0;
            }
            uint4* sp = (uint4*)(s_b + p * 16);
            sp[0] = make_uint4(vh0.x, vh1.x, vl0.x, vl1.x);
            sp[1] = make_uint4(vh0.y, vh1.y, vl0.y, vl1.y);
            sp[2] = make_uint4(vh0.z, vh1.z, vl0.z, vl1.z);
            sp[3] = make_uint4(vh0.w, vh1.w, vl0.w, vl1.w);
        }
        __syncthreads();

        load_frag(F0, 0);
        #pragma unroll 1
        for (int tap = 0; tap < KK; tap += 2) {
            if (tap + 1 < KK) load_frag(F1, tap + 1);
            compute_tap(F0, tap);
            if (tap + 1 < KK) {
                if (tap + 2 < KK) load_frag(F0, tap + 2);
                compute_tap(F1, tap + 1);
            }
        }
    }

    int rr = y0 + g;
    #pragma unroll
    for (int mt = 0; mt < 2; mt++) {
        int co0 = coB + mt * 16 + lr;
        float b0 = bias[co0];
        float b8 = bias[co0 + 8];
        #pragma unroll
        for (int nt = 0; nt < 5; nt++) {
            int xb = x0 + nt * 8 + 2 * lq;
            #pragma unroll
            for (int e = 0; e < 2; e++) {
                int x = xb + e;
                if (x >= 100) continue;
                int px = rr * 100 + x;
                float v0 = acc[mt][nt][e] + b0;
                float v8 = acc[mt][nt][2 + e] + b8;
                if (RES == 1) {
                    v0 += resid[(long)px * CO + co0];
                    v8 += resid[(long)px * CO + co0 + 8];
                } else if (RES == 2) {
                    v0 += resid[(long)co0 * HW + px];
                    v8 += resid[(long)(co0 + 8) * HW + px];
                }
                if (ACT == 1) { v0 = gelu_exact(v0); v8 = gelu_exact(v8); }
                if (WF) {
                    outf[(long)px * CO + co0] = v0;
                    outf[(long)px * CO + co0 + 8] = v8;
                }
                if (WS) {
                    long pp = (long)((rr + 2) * PW + x + 2) * CO;
                    unsigned short h, l;
                    split_bf16(v0, h, l); oh[pp + co0] = h; ol[pp + co0] = l;
                    split_bf16(v8, h, l); oh[pp + co0 + 8] = h; ol[pp + co0 + 8] = l;
                }
            }
        }
    }
}

__global__ void inorm_part_kernel(const float* __restrict__ in, float* __restrict__ part) {
    int blk = blockIdx.x;
    int tid = threadIdx.x;
    int c = tid & 127;
    int sub = tid >> 7;
    float s = 0.f, s2 = 0.f;
    for (int px = blk * 100 + sub; px < blk * 100 + 100; px += 2) {
        float v = in[(long)px * 128 + c];
        s += v;
        s2 = fmaf(v, v, s2);
    }
    __shared__ float sh1[256], sh2[256];
    sh1[tid] = s; sh2[tid] = s2;
    __syncthreads();
    if (tid < 128) {
        part[blk * 256 + tid] = sh1[tid] + sh1[tid + 128];
        part[blk * 256 + 128 + tid] = sh2[tid] + sh2[tid + 128];
    }
}
__global__ void inorm_final_kernel(const float* __restrict__ part, float* __restrict__ mv) {
    int tid = threadIdx.x;
    float s = 0.f;
    for (int b = 0; b < 100; b++) s += part[b * 256 + tid];
    __shared__ float sh[256];
    sh[tid] = s;
    __syncthreads();
    if (tid < 128) {
        float m = sh[tid] * 1e-4f;
        float v = sh[tid + 128] * 1e-4f - m * m;
        mv[tid] = m;
        mv[128 + tid] = rsqrtf(v + 1e-5f);
    }
}
template<int MODE>
__global__ void inorm_apply_kernel(const float* __restrict__ in, const float* __restrict__ mv,
                                   float* __restrict__ out,
                                   unsigned short* __restrict__ oh, unsigned short* __restrict__ ol) {
    int px = blockIdx.x;
    int c = threadIdx.x;
    float v = (in[(long)px * 128 + c] - mv[c]) * mv[128 + c];
    if (MODE == 1) out[(long)c * HW + px] = v;
    else out[(long)px * 128 + c] = v;
    if (MODE == 2) {
        int ppx = (px / 100 + 2) * PW + (px % 100) + 2;
        unsigned short h, l;
        split_bf16(v, h, l);
        oh[(long)ppx * 128 + c] = h;
        ol[(long)ppx * 128 + c] = l;
    }
}

__global__ void offsw_kernel(const float* __restrict__ q, const float* __restrict__ off_w,
                             const float* __restrict__ off_b, const float* __restrict__ sw_w,
                             const float* __restrict__ sw_b, const float* __restrict__ bev_pos,
                             float* __restrict__ ref_out, float* __restrict__ sw_out) {
    int pix = blockIdx.x;
    int tid = threadIdx.x;
    __shared__ float qv[128];
    __shared__ float logit[56];
    for (int c = tid; c < 128; c += 64) qv[c] = q[(long)pix * 128 + c];
    __syncthreads();
    if (tid < 24) {
        float s = off_b[tid];
        const float* wr = off_w + tid * 128;
        for (int c = 0; c < 128; c++) s = fmaf(qv[c], wr[c], s);
        logit[tid] = s;
    } else if (tid < 56) {
        int j = tid - 24;
        float s = sw_b[j];
        const float* wr = sw_w + j * 128;
        for (int c = 0; c < 128; c++) s = fmaf(qv[c], wr[c], s);
        logit[tid] = s;
    }
    __syncthreads();
    if (tid < 8) {
        int p = tid;
        const float lo[3] = {-50.f, -50.f, -5.f};
        const float span[3] = {100.f, 100.f, 8.f};
        const float rng = 0.25f + 1e-6f;
        const float zr = 4.0f + 1e-6f;
        #pragma unroll
        for (int d = 0; d < 3; d++) {
            float o = logit[p * 3 + d];
            float s = 1.0f / (1.0f + expf(-o));
            float off = (d < 2) ? (s * rng * 2.0f - rng) : (s * zr * 2.0f - zr);
            ref_out[pix * 24 + p * 3 + d] = bev_pos[pix * 3 + d] * span[d] + lo[d] + off;
        }
        float l0 = logit[24 + p * 4 + 0], l1 = logit[24 + p * 4 + 1];
        float l2 = logit[24 + p * 4 + 2], l3 = logit[24 + p * 4 + 3];
        float mx = fmaxf(fmaxf(l0, l1), fmaxf(l2, l3));
        float e0 = expf(l0 - mx), e1 = expf(l1 - mx);
        float e2 = expf(l2 - mx), e3 = expf(l3 - mx);
        float inv = 1.0f / (e0 + e1 + e2 + e3);
        sw_out[pix * 32 + p * 4 + 0] = e0 * inv;
        sw_out[pix * 32 + p * 4 + 1] = e1 * inv;
        sw_out[pix * 32 + p * 4 + 2] = e2 * inv;
        sw_out[pix * 32 + p * 4 + 3] = e3 * inv;
    }
}

__global__ void sample_kernel(const float* __restrict__ featT, const float* __restrict__ ref,
                              const float* __restrict__ swl, const float* __restrict__ lidar2img,
                              unsigned short* __restrict__ sfh, unsigned short* __restrict__ sfl) {
    int pix = blockIdx.x;
    int tid = threadIdx.x;
    __shared__ float Mm[96];
    __shared__ float refs[24];
    __shared__ float sws[32];
    __shared__ float pos3d[3];
    if (tid < 96) Mm[tid] = lidar2img[tid];
    if (tid < 24) refs[tid] = ref[pix * 24 + tid];
    if (tid < 32) sws[tid] = swl[pix * 32 + tid];
    __syncthreads();

    const int LH[4] = {32, 16, 8, 4};
    const int LW[4] = {88, 44, 22, 11};
    const int LOFF[4] = {L0_OFF, L1_OFF, L2_OFF, L3_OFF};

    float sfeat = 0.f, sweight = 0.f;
    for (int p = 0; p < 8; p++) {
        float acc = 0.f, acc3 = 0.f;
        float rx = refs[p * 3 + 0], ry = refs[p * 3 + 1], rz = refs[p * 3 + 2];
        for (int n = 0; n < 6; n++) {
            const float* M = Mm + n * 16;
            float cz = M[8] * rx + M[9] * ry + M[10] * rz + M[11];
            if (cz <= 1e-5f) continue;
            float cx = (M[0] * rx + M[1] * ry + M[2] * rz + M[3]) / cz;
            float cy = (M[4] * rx + M[5] * ry + M[6] * rz + M[7]) / cz;
            float gx = cx / 704.0f * 2.0f - 1.0f;
            float gy = cy / 256.0f * 2.0f - 1.0f;
            #pragma unroll
            for (int l = 0; l < 4; l++) {
                float wl = sws[p * 4 + l];
                float fx = (gx + 1.0f) * 0.5f * LW[l] - 0.5f;
                float fy = (gy + 1.0f) * 0.5f * LH[l] - 0.5f;
                float x0f = floorf(fx), y0f = floorf(fy);
                float wx = fx - x0f, wy = fy - y0f;
                int ix = (int)x0f, iy = (int)y0f;
                float w00 = (1.f - wx) * (1.f - wy) * wl;
                float w10 = wx * (1.f - wy) * wl;
                float w01 = (1.f - wx) * wy * wl;
                float w11 = wx * wy * wl;
                #pragma unroll
                for (int t = 0; t < 4; t++) {
                    int xi = ix + (t & 1);
                    int yi = iy + (t >> 1);
                    float cw = (t == 0) ? w00 : (t == 1) ? w10 : (t == 2) ? w01 : w11;
                    if (xi >= 0 && xi < LW[l] && yi >= 0 && yi < LH[l]) {
                        const float* fp = featT + LOFF[l] + ((long)(n * LH[l] + yi) * LW[l] + xi) * 132;
                        acc = fmaf(cw, fp[tid], acc);
                        if (tid < 3) acc3 = fmaf(cw, fp[128 + tid], acc3);
                    }
                }
            }
        }
        if (tid < 3) pos3d[tid] = acc3;
        __syncthreads();
        float dx = rx - pos3d[0], dy = ry - pos3d[1], dz = rz - pos3d[2];
        float wgt = expf(-0.1f * (dx * dx + dy * dy + dz * dz));
        sfeat += acc;
        sweight += acc * wgt;
        __syncthreads();
    }
    int ppx = (pix / 100 + 2) * PW + (pix % 100) + 2;
    unsigned short h, l;
    split_bf16(sfeat, h, l);
    sfh[(long)ppx * 256 + tid] = h;
    sfl[(long)ppx * 256 + tid] = l;
    split_bf16(sweight, h, l);
    sfh[(long)ppx * 256 + 128 + tid] = h;
    sfl[(long)ppx * 256 + 128 + tid] = l;
}

extern "C" void kernel_launch(void* const* d_in, const int* in_sizes, int n_in,
                              void* d_out, int out_size) {
    const float* bev_query = (const float*)d_in[0];
    const float* bev_pos   = (const float*)d_in[1];
    const float* lidar2img = (const float*)d_in[2];
    const float* feat0 = (const float*)d_in[3];
    const float* feat1 = (const float*)d_in[4];
    const float* feat2 = (const float*)d_in[5];
    const float* feat3 = (const float*)d_in[6];
    const float* in_w  = (const float*)d_in[7];
    const float* in_b  = (const float*)d_in[8];
    const float* off_w = (const float*)d_in[9];
    const float* off_b = (const float*)d_in[10];
    const float* sw_w  = (const float*)d_in[11];
    const float* sw_b  = (const float*)d_in[12];
    const float* mid_w1 = (const float*)d_in[13];
    const float* mid_b1 = (const float*)d_in[14];
    const float* mid_w2 = (const float*)d_in[15];
    const float* mid_b2 = (const float*)d_in[16];
    const float* mid_w3 = (const float*)d_in[17];
    const float* mid_b3 = (const float*)d_in[18];
    const float* out_w = (const float*)d_in[19];
    const float* out_b = (const float*)d_in[20];
    float* out = (float*)d_out;

    float *buf, *q, *q2, *refp, *swp, *featT, *part, *mv;
    cudaGetSymbolAddress((void**)&buf, g_buf);
    cudaGetSymbolAddress((void**)&q, g_q);
    cudaGetSymbolAddress((void**)&q2, g_q2);
    cudaGetSymbolAddress((void**)&refp, g_ref);
    cudaGetSymbolAddress((void**)&swp, g_swl);
    cudaGetSymbolAddress((void**)&featT, g_featT);
    cudaGetSymbolAddress((void**)&part, g_part);
    cudaGetSymbolAddress((void**)&mv, g_mv);

    unsigned short *bqph,*bqpl,*sfph,*sfpl,*m1ph,*m1pl,*m2ph,*m2pl,*q2ph,*q2pl;
    uint4 *p1,*p2,*p3,*p4,*p5;
    cudaGetSymbolAddress((void**)&bqph, g_bqp_h); cudaGetSymbolAddress((void**)&bqpl, g_bqp_l);
    cudaGetSymbolAddress((void**)&sfph, g_sfp_h); cudaGetSymbolAddress((void**)&sfpl, g_sfp_l);
    cudaGetSymbolAddress((void**)&m1ph, g_m1p_h); cudaGetSymbolAddress((void**)&m1pl, g_m1p_l);
    cudaGetSymbolAddress((void**)&m2ph, g_m2p_h); cudaGetSymbolAddress((void**)&m2pl, g_m2p_l);
    cudaGetSymbolAddress((void**)&q2ph, g_q2p_h); cudaGetSymbolAddress((void**)&q2pl, g_q2p_l);
    cudaGetSymbolAddress((void**)&p1, g_wp1);
    cudaGetSymbolAddress((void**)&p2, g_wp2);
    cudaGetSymbolAddress((void**)&p3, g_wp3);
    cudaGetSymbolAddress((void**)&p4, g_wp4);
    cudaGetSymbolAddress((void**)&p5, g_wp5);

    wprep_all<<<(712704 + 255) / 256, 256>>>(in_w, mid_w1, mid_w2, mid_w3, out_w,
                                             p1, p2, p3, p4, p5);
    padsplit_cm_kernel<<<PPX, 128>>>(bev_query, bqph, bqpl);
    transpose_all<<<(2962080 + 255) / 256, 256>>>(feat0, feat1, feat2, feat3, featT);

    conv_mma_kernel<128,128,5,2,0,2,1,0><<<dim3(150,1), 256>>>(
        bqph, bqpl, p1, in_b, bev_query, buf, nullptr, nullptr);
    inorm_part_kernel<<<100, 256>>>(buf, part);
    inorm_final_kernel<<<1, 256>>>(part, mv);
    inorm_apply_kernel<0><<<HW, 128>>>(buf, mv, q, nullptr, nullptr);

    offsw_kernel<<<HW, 64>>>(q, off_w, off_b, sw_w, sw_b, bev_pos, refp, swp);
    sample_kernel<<<HW, 128>>>(featT, refp, swp, lidar2img, sfph, sfpl);

    conv_mma_kernel<256,512,3,1,1,0,0,1><<<dim3(150,4), 256>>>(
        sfph, sfpl, p2, mid_b1, nullptr, nullptr, m1ph, m1pl);
    conv_mma_kernel<512,512,1,0,1,0,0,1><<<dim3(150,4), 256>>>(
        m1ph, m1pl, p3, mid_b2, nullptr, nullptr, m2ph, m2pl);
    conv_mma_kernel<512,128,3,1,0,1,1,0><<<dim3(150,1), 256>>>(
        m2ph, m2pl, p4, mid_b3, q, buf, nullptr, nullptr);
    inorm_part_kernel<<<100, 256>>>(buf, part);
    inorm_final_kernel<<<1, 256>>>(part, mv);
    inorm_apply_kernel<2><<<HW, 128>>>(buf, mv, q2, q2ph, q2pl);

    conv_mma_kernel<128,128,5,2,0,1,1,0><<<dim3(150,1), 256>>>(
        q2ph, q2pl, p5, out_b, q2, buf, nullptr, nullptr);
    inorm_part_kernel<<<100, 256>>>(buf, part);
    inorm_final_kernel<<<1, 256>>>(part, mv);
    inorm_apply_kernel<1><<<HW, 128>>>(buf, mv, out, nullptr, nullptr);
}